// round 4
// baseline (speedup 1.0000x reference)
#include <cuda_runtime.h>
#include <cuda_fp16.h>
#include <math.h>
#include <float.h>

// Problem constants
#define BN 16
#define NN 1024
#define UU 64
#define KDIM 128        // 2U
#define MAXD 128        // max neighbor degree (avg ~33)
#define ALPHA 0.2f

// ---------------- scratch (device globals; no allocation allowed) ----------------
__device__ __half g_h1[BN * NN * 128];    // layer-1 features (fp16 gather copy)
__device__ __half g_h2[BN * NN * UU];     // layer-2 features
__device__ float g_ssrc1[BN * NN];
__device__ float g_sdst1[BN * NN];
__device__ float g_ssrc2[BN * NN];
__device__ float g_sdst2[BN * NN];
__device__ float g_z[BN * NN * UU];       // gate z
__device__ float g_rs[BN * NN * UU];      // r * state
__device__ int   g_nbr[NN * MAXD];
__device__ int   g_cnt[NN];

// ---------------- neighbor list build (deterministic, ascending j) ----------------
__global__ void build_nbr_kernel(const float* __restrict__ adj) {
    int i = blockIdx.x;
    int tid = threadIdx.x;             // 128 threads
    int lane = tid & 31, wid = tid >> 5;
    __shared__ int wcnt[4];
    __shared__ int sbase;
    if (tid == 0) sbase = 0;
    __syncthreads();
    for (int j0 = 0; j0 < NN; j0 += 128) {
        int j = j0 + tid;
        bool p = adj[i * NN + j] > 0.0f;
        unsigned ball = __ballot_sync(0xffffffffu, p);
        if (lane == 0) wcnt[wid] = __popc(ball);
        __syncthreads();
        int off = sbase;
#pragma unroll
        for (int w = 0; w < 4; w++) if (w < wid) off += wcnt[w];
        int tot = wcnt[0] + wcnt[1] + wcnt[2] + wcnt[3];
        if (p) {
            int pos = off + __popc(ball & ((1u << lane) - 1u));
            if (pos < MAXD) g_nbr[i * MAXD + pos] = j;
        }
        __syncthreads();
        if (tid == 0) sbase += tot;
    }
    __syncthreads();
    if (tid == 0) g_cnt[i] = (sbase < MAXD) ? sbase : MAXD;
}

// ---------------- fused-concat GEMM + fp16 store + fused attention scores ----------------
// 128 threads, 32-row tile, full F cols per block. Thread: 4 rows x F cols (vectorized).
template <int F, int LAYER>
__global__ void __launch_bounds__(128, 8)
gemm_cat_kernel(const float* __restrict__ X,
                const float* __restrict__ S,
                const float* __restrict__ W,
                const float* __restrict__ a) {
    constexpr int RT = 32;        // rows per block
    constexpr int KC = 32;        // K chunk
    constexpr int NG = F / 64;    // col groups of 4 per thread (via 16 tx lanes)
    constexpr int XP = 36;        // padded X row (floats), 16B aligned stride
    constexpr int WP = F + 4;     // padded W row

    __shared__ float Xs[KC][XP];
    __shared__ float Ws[KC][WP];

    const float* Ssrc = (LAYER == 1) ? S : g_rs;
    __half*      H    = (LAYER == 1) ? g_h1 : g_h2;
    float*       ssrc = (LAYER == 1) ? g_ssrc1 : g_ssrc2;
    float*       sdst = (LAYER == 1) ? g_sdst1 : g_sdst2;

    int tid = threadIdx.x;
    int tx = tid & 15;            // col group
    int ty = tid >> 4;            // row group (0..7), rows 4*ty..4*ty+3
    int row0 = blockIdx.x * RT;

    float acc[4][NG][4];
#pragma unroll
    for (int r = 0; r < 4; r++)
#pragma unroll
        for (int g = 0; g < NG; g++)
#pragma unroll
            for (int c = 0; c < 4; c++) acc[r][g][c] = 0.0f;

    for (int k0 = 0; k0 < KDIM; k0 += KC) {
        const float* src = (k0 < UU) ? X : Ssrc;
        int colOff = k0 & (UU - 1);
        // stage X tile: RT*KC floats = 256 float4, 2 per thread
#pragma unroll
        for (int it = 0; it < 2; it++) {
            int idx = tid + it * 128;
            int r = idx >> 3;             // row 0..31
            int k4 = idx & 7;             // k group of 4
            float4 v = *(const float4*)&src[(row0 + r) * UU + colOff + 4 * k4];
            Xs[4 * k4 + 0][r] = v.x;
            Xs[4 * k4 + 1][r] = v.y;
            Xs[4 * k4 + 2][r] = v.z;
            Xs[4 * k4 + 3][r] = v.w;
        }
        // stage W tile: KC*F floats
#pragma unroll
        for (int it = 0; it < KC * F / 512; it++) {
            int idx = tid + it * 128;
            int k = idx / (F / 4);
            int c4 = idx - k * (F / 4);
            float4 v = *(const float4*)&W[(k0 + k) * F + 4 * c4];
            *(float4*)&Ws[k][4 * c4] = v;
        }
        __syncthreads();
#pragma unroll
        for (int k = 0; k < KC; k++) {
            float4 xa = *(const float4*)&Xs[k][4 * ty];
#pragma unroll
            for (int g = 0; g < NG; g++) {
                float4 wb = *(const float4*)&Ws[k][4 * tx + 64 * g];
                acc[0][g][0] = fmaf(xa.x, wb.x, acc[0][g][0]);
                acc[0][g][1] = fmaf(xa.x, wb.y, acc[0][g][1]);
                acc[0][g][2] = fmaf(xa.x, wb.z, acc[0][g][2]);
                acc[0][g][3] = fmaf(xa.x, wb.w, acc[0][g][3]);
                acc[1][g][0] = fmaf(xa.y, wb.x, acc[1][g][0]);
                acc[1][g][1] = fmaf(xa.y, wb.y, acc[1][g][1]);
                acc[1][g][2] = fmaf(xa.y, wb.z, acc[1][g][2]);
                acc[1][g][3] = fmaf(xa.y, wb.w, acc[1][g][3]);
                acc[2][g][0] = fmaf(xa.z, wb.x, acc[2][g][0]);
                acc[2][g][1] = fmaf(xa.z, wb.y, acc[2][g][1]);
                acc[2][g][2] = fmaf(xa.z, wb.z, acc[2][g][2]);
                acc[2][g][3] = fmaf(xa.z, wb.w, acc[2][g][3]);
                acc[3][g][0] = fmaf(xa.w, wb.x, acc[3][g][0]);
                acc[3][g][1] = fmaf(xa.w, wb.y, acc[3][g][1]);
                acc[3][g][2] = fmaf(xa.w, wb.z, acc[3][g][2]);
                acc[3][g][3] = fmaf(xa.w, wb.w, acc[3][g][3]);
            }
        }
        __syncthreads();
    }

    // hoist attention vector slices
    float av1[NG][4], av2[NG][4];
#pragma unroll
    for (int g = 0; g < NG; g++)
#pragma unroll
        for (int c = 0; c < 4; c++) {
            int col = 4 * tx + 64 * g + c;
            av1[g][c] = a[col];
            av2[g][c] = a[F + col];
        }

    // epilogue: fp16 store + fused scores
#pragma unroll
    for (int r = 0; r < 4; r++) {
        int row = row0 + 4 * ty + r;
        __half2* Hrow = (__half2*)(H + (size_t)row * F);
        float s1 = 0.0f, s2 = 0.0f;
#pragma unroll
        for (int g = 0; g < NG; g++) {
            Hrow[2 * tx + 32 * g]     = __floats2half2_rn(acc[r][g][0], acc[r][g][1]);
            Hrow[2 * tx + 32 * g + 1] = __floats2half2_rn(acc[r][g][2], acc[r][g][3]);
#pragma unroll
            for (int c = 0; c < 4; c++) {
                s1 = fmaf(acc[r][g][c], av1[g][c], s1);
                s2 = fmaf(acc[r][g][c], av2[g][c], s2);
            }
        }
#pragma unroll
        for (int off = 8; off > 0; off >>= 1) {
            s1 += __shfl_xor_sync(0xffffffffu, s1, off);
            s2 += __shfl_xor_sync(0xffffffffu, s2, off);
        }
        if (tx == 0) { ssrc[row] = s1; sdst[row] = s2; }
    }
}

// ---------------- masked-softmax attention + fp16 gather + epilogue ----------------
// Block = (i, batch-group BPB). blockDim = BPB * F/2 (each thread: one __half2 pair).
template <int F, int BPB, int LAYER>
__global__ void attn_kernel(const float* __restrict__ state, float* __restrict__ out) {
    constexpr int F2 = F / 2;
    const __half* H   = (LAYER == 1) ? g_h1 : g_h2;
    const float* ssrc = (LAYER == 1) ? g_ssrc1 : g_ssrc2;
    const float* sdst = (LAYER == 1) ? g_sdst1 : g_sdst2;

    int i  = blockIdx.x;
    int b0 = blockIdx.y * BPB;
    int tid  = threadIdx.x;
    int lane = tid & 31;
    int wid  = tid >> 5;

    __shared__ int   sj[MAXD];
    __shared__ float sw[BPB][MAXD];
    __shared__ int   scnt;

    if (tid == 0) scnt = g_cnt[i];
    __syncthreads();
    int cnt  = scnt;
    int cntR = (cnt + 7) & ~7;            // rounded for branch-free unroll-8
    // load + pad neighbor indices (pad with i — always a valid row)
    for (int k = tid; k < MAXD; k += BPB * F2)
        sj[k] = (k < cnt) ? g_nbr[i * MAXD + k] : i;
    __syncthreads();

    // ---- phase 1: per-warp softmax for one batch (pre-normalized weights) ----
    if (wid < BPB) {
        int b = b0 + wid;
        float si = ssrc[b * NN + i];
        const float* sd = sdst + b * NN;
        float ee[MAXD / 32];
        float m = -FLT_MAX;
#pragma unroll
        for (int u = 0; u < MAXD / 32; u++) {
            int k = lane + 32 * u;
            float e = -FLT_MAX;
            if (k < cnt) {
                float v = si + sd[sj[k]];
                e = (v > 0.0f) ? v : ALPHA * v;
            }
            ee[u] = e;
            m = fmaxf(m, e);
        }
#pragma unroll
        for (int off = 16; off > 0; off >>= 1)
            m = fmaxf(m, __shfl_xor_sync(0xffffffffu, m, off));
        float s = 0.0f;
#pragma unroll
        for (int u = 0; u < MAXD / 32; u++) {
            int k = lane + 32 * u;
            if (k < cnt) {
                float w = __expf(ee[u] - m);
                ee[u] = w;
                s += w;
            }
        }
#pragma unroll
        for (int off = 16; off > 0; off >>= 1)
            s += __shfl_xor_sync(0xffffffffu, s, off);
        float inv = 1.0f / s;
#pragma unroll
        for (int u = 0; u < MAXD / 32; u++) {
            int k = lane + 32 * u;
            if (k < cnt)      sw[wid][k] = ee[u] * inv;
            else if (k < cntR) sw[wid][k] = 0.0f;
        }
    }
    __syncthreads();

    // ---- phase 2: fp16 gather-aggregate (__half2 per thread, unroll-8 MLP) ----
    int bb = tid / F2;
    int f2 = tid - bb * F2;
    int b  = b0 + bb;
    const __half2* Hb2 = (const __half2*)H + (size_t)(b * NN) * F2 + f2;
    const float* wrow = sw[bb];

    float ax0 = 0.0f, ay0 = 0.0f, ax1 = 0.0f, ay1 = 0.0f;
    float ax2 = 0.0f, ay2 = 0.0f, ax3 = 0.0f, ay3 = 0.0f;
    for (int k = 0; k < cntR; k += 8) {
        int j0 = sj[k],     j1 = sj[k + 1], j2 = sj[k + 2], j3 = sj[k + 3];
        int j4 = sj[k + 4], j5 = sj[k + 5], j6 = sj[k + 6], j7 = sj[k + 7];
        float2 h0 = __half22float2(Hb2[(size_t)j0 * F2]);
        float2 h1 = __half22float2(Hb2[(size_t)j1 * F2]);
        float2 h2 = __half22float2(Hb2[(size_t)j2 * F2]);
        float2 h3 = __half22float2(Hb2[(size_t)j3 * F2]);
        float2 h4 = __half22float2(Hb2[(size_t)j4 * F2]);
        float2 h5 = __half22float2(Hb2[(size_t)j5 * F2]);
        float2 h6 = __half22float2(Hb2[(size_t)j6 * F2]);
        float2 h7 = __half22float2(Hb2[(size_t)j7 * F2]);
        float w0 = wrow[k],     w1 = wrow[k + 1], w2 = wrow[k + 2], w3 = wrow[k + 3];
        float w4 = wrow[k + 4], w5 = wrow[k + 5], w6 = wrow[k + 6], w7 = wrow[k + 7];
        ax0 = fmaf(w0, h0.x, ax0); ay0 = fmaf(w0, h0.y, ay0);
        ax1 = fmaf(w1, h1.x, ax1); ay1 = fmaf(w1, h1.y, ay1);
        ax2 = fmaf(w2, h2.x, ax2); ay2 = fmaf(w2, h2.y, ay2);
        ax3 = fmaf(w3, h3.x, ax3); ay3 = fmaf(w3, h3.y, ay3);
        ax0 = fmaf(w4, h4.x, ax0); ay0 = fmaf(w4, h4.y, ay0);
        ax1 = fmaf(w5, h5.x, ax1); ay1 = fmaf(w5, h5.y, ay1);
        ax2 = fmaf(w6, h6.x, ax2); ay2 = fmaf(w6, h6.y, ay2);
        ax3 = fmaf(w7, h7.x, ax3); ay3 = fmaf(w7, h7.y, ay3);
    }
    float accx = (ax0 + ax1) + (ax2 + ax3);
    float accy = (ay0 + ay1) + (ay2 + ay3);

    int base = (b * NN + i) * UU;
    if (LAYER == 1) {
        float gx = 1.0f / (1.0f + __expf(-accx));
        float gy = 1.0f / (1.0f + __expf(-accy));
        if (f2 < UU / 2) {
            const float2 st = ((const float2*)(state + base))[f2];
            float2 rs; rs.x = gx * st.x; rs.y = gy * st.y;
            ((float2*)(g_rs + base))[f2] = rs;
        } else {
            float2 zz; zz.x = gx; zz.y = gy;
            ((float2*)(g_z + base))[f2 - UU / 2] = zz;
        }
    } else {
        float htx = tanhf(accx);
        float hty = tanhf(accy);
        const float2 st = ((const float2*)(state + base))[f2];
        const float2 zz = ((const float2*)(g_z + base))[f2];
        float2 o;
        o.x = fmaf(zz.x, st.x, (1.0f - zz.x) * htx);
        o.y = fmaf(zz.y, st.y, (1.0f - zz.y) * hty);
        ((float2*)(out + base))[f2] = o;
    }
}

// ---------------- launch ----------------
extern "C" void kernel_launch(void* const* d_in, const int* in_sizes, int n_in,
                              void* d_out, int out_size) {
    const float* X     = (const float*)d_in[0];
    const float* state = (const float*)d_in[1];
    const float* adj   = (const float*)d_in[2];
    const float* W1    = (const float*)d_in[3];
    const float* a1    = (const float*)d_in[4];
    const float* W2    = (const float*)d_in[5];
    const float* a2    = (const float*)d_in[6];
    float* out = (float*)d_out;

    // 1) neighbor lists (deterministic)
    build_nbr_kernel<<<NN, 128>>>(adj);

    // 2) layer 1: h1 = [X||state] @ W1  (+ fused scores, fp16 H)
    gemm_cat_kernel<128, 1><<<(BN * NN) / 32, 128>>>(X, state, W1, a1);

    // 3) attention layer 1 (+ sigmoid, r*state, z) — 4 batches/block, 256 thr
    attn_kernel<128, 4, 1><<<dim3(NN, BN / 4), 256>>>(state, out);

    // 4) layer 2: h2 = [X||r*state] @ W2  (+ fused scores, fp16 H)
    gemm_cat_kernel<64, 2><<<(BN * NN) / 32, 128>>>(X, state, W2, a2);

    // 5) attention layer 2 (+ tanh + GRU gate -> out) — 8 batches/block, 256 thr
    attn_kernel<64, 8, 2><<<dim3(NN, BN / 8), 256>>>(state, out);
}

// round 9
// speedup vs baseline: 1.4389x; 1.4389x over previous
#include <cuda_runtime.h>
#include <cuda_fp16.h>
#include <mma.h>
#include <math.h>
#include <float.h>

using namespace nvcuda;

// Problem constants
#define BN 16
#define NN 1024
#define UU 64
#define KDIM 128
#define MAXD 128
#define ALPHA 0.2f

// ---------------- scratch (device globals; no allocation allowed) ----------------
__device__ __half g_h1[BN * NN * 128];
__device__ __half g_h2[BN * NN * UU];
__device__ float g_ssrc1[BN * NN];
__device__ float g_sdst1[BN * NN];
__device__ float g_ssrc2[BN * NN];
__device__ float g_sdst2[BN * NN];
__device__ float g_z[BN * NN * UU];
__device__ float g_rs[BN * NN * UU];
__device__ int   g_nbr[NN * MAXD];
__device__ int   g_cnt[NN];

// ---------------- neighbor list build (deterministic, ascending j) ----------------
__global__ void build_nbr_kernel(const float* __restrict__ adj) {
    int i = blockIdx.x;
    int tid = threadIdx.x;
    int lane = tid & 31;
    int wid = tid >> 5;
    __shared__ int wcnt[4];
    __shared__ int sbase;
    if (tid == 0) sbase = 0;
    __syncthreads();
    for (int j0 = 0; j0 < NN; j0 += 128) {
        int j = j0 + tid;
        bool p = adj[i * NN + j] > 0.0f;
        unsigned ball = __ballot_sync(0xffffffffu, p);
        if (lane == 0) wcnt[wid] = __popc(ball);
        __syncthreads();
        int off = sbase;
        if (wid > 0) off += wcnt[0];
        if (wid > 1) off += wcnt[1];
        if (wid > 2) off += wcnt[2];
        int tot = wcnt[0] + wcnt[1] + wcnt[2] + wcnt[3];
        if (p) {
            int pos = off + __popc(ball & ((1u << lane) - 1u));
            if (pos < MAXD) g_nbr[i * MAXD + pos] = j;
        }
        __syncthreads();
        if (tid == 0) sbase += tot;
    }
    __syncthreads();
    if (tid == 0) g_cnt[i] = (sbase < MAXD) ? sbase : MAXD;
}

// ---------------- tensor-core fused-concat GEMM (wmma) + scores + fp16 H ----------------
// CTA: 256 thr (8 warps = 4 M-groups x 2 N-groups), M-tile 64, full F, K chunked at 64.
template <int F, int LAYER>
__global__ void __launch_bounds__(256)
gemm_wmma_kernel(const float* __restrict__ X,
                 const float* __restrict__ S,
                 const float* __restrict__ W,
                 const float* __restrict__ a) {
    constexpr int MT = 64;
    constexpr int AS = 72;              // A row stride (halves): 64 + 8
    constexpr int WS = F + 8;           // W row stride (halves)
    constexpr int CS = F + 4;           // C row stride (floats)
    constexpr int NFRAG = F / 32;       // 16-col frags per warp (warp covers F/2)
    constexpr int A_BYTES = MT * AS * 2;
    constexpr int W_BYTES = 64 * WS * 2;
    constexpr int C_BYTES = MT * CS * 4;
    constexpr int STAGE_BYTES = A_BYTES + W_BYTES;
    constexpr int SMEM_BYTES = (C_BYTES > STAGE_BYTES) ? C_BYTES : STAGE_BYTES;

    __shared__ __align__(16) char smem_raw[SMEM_BYTES];
    __half* As = (__half*)smem_raw;                       // [MT][AS]
    __half* Ws = (__half*)(smem_raw + A_BYTES);           // [64][WS]
    float*  Cs = (float*)smem_raw;                        // [MT][CS] (after mainloop)

    const float* Ssrc = (LAYER == 1) ? S : g_rs;
    __half*      H    = (LAYER == 1) ? g_h1 : g_h2;
    float*       ssrc = (LAYER == 1) ? g_ssrc1 : g_ssrc2;
    float*       sdst = (LAYER == 1) ? g_sdst1 : g_sdst2;

    int tid = threadIdx.x;
    int lane = tid & 31;
    int wid = tid >> 5;
    int row0 = blockIdx.x * MT;

    int mw = wid >> 1;                  // 0..3 : 16-row group
    int nw = wid & 1;                   // 0..1 : F/2-col group
    int m0 = mw * 16;
    int n0w = nw * (F / 2);

    wmma::fragment<wmma::accumulator, 16, 16, 16, float> facc[NFRAG];
    for (int nf = 0; nf < NFRAG; nf++) {
        wmma::fill_fragment(facc[nf], 0.0f);
    }

    for (int kc = 0; kc < 2; kc++) {
        const float* src = (kc == 0) ? X : Ssrc;
        // stage A chunk: 64 rows x 64 cols fp32 -> fp16
        for (int it = 0; it < 4; it++) {
            int idx = tid + it * 256;        // 0..1023
            int r = idx >> 4;
            int c4 = idx & 15;
            float4 v = *(const float4*)(src + (row0 + r) * UU + 4 * c4);
            __half2* dst = (__half2*)(As + r * AS + 4 * c4);
            dst[0] = __floats2half2_rn(v.x, v.y);
            dst[1] = __floats2half2_rn(v.z, v.w);
        }
        // stage W chunk: rows kc*64 .. kc*64+63, F cols fp32 -> fp16
        for (int it = 0; it < F / 16; it++) {
            int idx = tid + it * 256;
            int r = idx / (F / 4);
            int c4 = idx - r * (F / 4);
            float4 v = *(const float4*)(W + (kc * 64 + r) * F + 4 * c4);
            __half2* dst = (__half2*)(Ws + r * WS + 4 * c4);
            dst[0] = __floats2half2_rn(v.x, v.y);
            dst[1] = __floats2half2_rn(v.z, v.w);
        }
        __syncthreads();

        for (int ks = 0; ks < 4; ks++) {
            int k0 = ks * 16;
            wmma::fragment<wmma::matrix_a, 16, 16, 16, __half, wmma::row_major> fa;
            wmma::load_matrix_sync(fa, As + m0 * AS + k0, AS);
            for (int nf = 0; nf < NFRAG; nf++) {
                wmma::fragment<wmma::matrix_b, 16, 16, 16, __half, wmma::row_major> fb;
                wmma::load_matrix_sync(fb, Ws + k0 * WS + n0w + nf * 16, WS);
                wmma::mma_sync(facc[nf], fa, fb, facc[nf]);
            }
        }
        __syncthreads();
    }

    // spill accumulators to shared C (reuses staging memory)
    for (int nf = 0; nf < NFRAG; nf++) {
        wmma::store_matrix_sync(Cs + m0 * CS + n0w + nf * 16, facc[nf], CS, wmma::mem_row_major);
    }
    __syncthreads();

    // epilogue A: fp16 H copy (256 threads over 64 x F/2 half2)
    for (int it = 0; it < MT * F / 512; it++) {
        int idx = tid + it * 256;
        int r = idx / (F / 2);
        int c2 = idx - r * (F / 2);
        float v0 = Cs[r * CS + 2 * c2];
        float v1 = Cs[r * CS + 2 * c2 + 1];
        ((__half2*)(H + (size_t)(row0 + r) * F))[c2] = __floats2half2_rn(v0, v1);
    }

    // epilogue B: fused scores — warp wid handles rows wid*8 .. wid*8+7
    for (int rr = 0; rr < 8; rr++) {
        int r = wid * 8 + rr;
        float s1 = 0.0f;
        float s2 = 0.0f;
        for (int c = lane; c < F; c += 32) {
            float hv = Cs[r * CS + c];
            s1 = fmaf(hv, a[c], s1);
            s2 = fmaf(hv, a[F + c], s2);
        }
        for (int off = 16; off > 0; off >>= 1) {
            s1 += __shfl_xor_sync(0xffffffffu, s1, off);
            s2 += __shfl_xor_sync(0xffffffffu, s2, off);
        }
        if (lane == 0) {
            ssrc[row0 + r] = s1;
            sdst[row0 + r] = s2;
        }
    }
}

// ---------------- masked-softmax attention + fp16 gather + epilogue ----------------
template <int F, int BPB, int LAYER>
__global__ void attn_kernel(const float* __restrict__ state, float* __restrict__ out) {
    constexpr int F2 = F / 2;
    const __half* H   = (LAYER == 1) ? g_h1 : g_h2;
    const float* ssrc = (LAYER == 1) ? g_ssrc1 : g_ssrc2;
    const float* sdst = (LAYER == 1) ? g_sdst1 : g_sdst2;

    int i  = blockIdx.x;
    int b0 = blockIdx.y * BPB;
    int tid  = threadIdx.x;
    int lane = tid & 31;
    int wid  = tid >> 5;

    __shared__ int   sj[MAXD];
    __shared__ float sw[BPB][MAXD];
    __shared__ int   scnt;

    if (tid == 0) scnt = g_cnt[i];
    for (int k = tid; k < MAXD; k += BPB * F2) sj[k] = g_nbr[i * MAXD + k];
    __syncthreads();
    int cnt = scnt;

    // phase 1: per-warp softmax (pre-normalized weights)
    if (wid < BPB) {
        int b = b0 + wid;
        float si = ssrc[b * NN + i];
        const float* sd = sdst + b * NN;
        float ee[MAXD / 32];
        float m = -FLT_MAX;
        for (int u = 0; u < MAXD / 32; u++) {
            int k = lane + 32 * u;
            float e = -FLT_MAX;
            if (k < cnt) {
                float v = si + sd[sj[k]];
                e = (v > 0.0f) ? v : ALPHA * v;
            }
            ee[u] = e;
            m = fmaxf(m, e);
        }
        for (int off = 16; off > 0; off >>= 1) {
            m = fmaxf(m, __shfl_xor_sync(0xffffffffu, m, off));
        }
        float s = 0.0f;
        for (int u = 0; u < MAXD / 32; u++) {
            int k = lane + 32 * u;
            if (k < cnt) {
                float w = __expf(ee[u] - m);
                ee[u] = w;
                s += w;
            }
        }
        for (int off = 16; off > 0; off >>= 1) {
            s += __shfl_xor_sync(0xffffffffu, s, off);
        }
        float inv = 1.0f / s;
        for (int u = 0; u < MAXD / 32; u++) {
            int k = lane + 32 * u;
            if (k < cnt) sw[wid][k] = ee[u] * inv;
        }
    }
    __syncthreads();

    // phase 2: fp16 gather-aggregate (__half2 per thread, unroll-4 MLP)
    int bb = tid / F2;
    int f2 = tid - bb * F2;
    int b  = b0 + bb;
    const __half2* Hb2 = (const __half2*)H + (size_t)(b * NN) * F2 + f2;
    const float* wrow = sw[bb];

    float ax0 = 0.0f;
    float ay0 = 0.0f;
    float ax1 = 0.0f;
    float ay1 = 0.0f;
    int k = 0;
    for (; k + 4 <= cnt; k += 4) {
        int j0 = sj[k];
        int j1 = sj[k + 1];
        int j2 = sj[k + 2];
        int j3 = sj[k + 3];
        float w0 = wrow[k];
        float w1 = wrow[k + 1];
        float w2 = wrow[k + 2];
        float w3 = wrow[k + 3];
        float2 h0 = __half22float2(Hb2[(size_t)j0 * F2]);
        float2 h1 = __half22float2(Hb2[(size_t)j1 * F2]);
        float2 h2 = __half22float2(Hb2[(size_t)j2 * F2]);
        float2 h3 = __half22float2(Hb2[(size_t)j3 * F2]);
        ax0 = fmaf(w0, h0.x, ax0);
        ay0 = fmaf(w0, h0.y, ay0);
        ax1 = fmaf(w1, h1.x, ax1);
        ay1 = fmaf(w1, h1.y, ay1);
        ax0 = fmaf(w2, h2.x, ax0);
        ay0 = fmaf(w2, h2.y, ay0);
        ax1 = fmaf(w3, h3.x, ax1);
        ay1 = fmaf(w3, h3.y, ay1);
    }
    for (; k < cnt; k++) {
        float2 h = __half22float2(Hb2[(size_t)sj[k] * F2]);
        ax0 = fmaf(wrow[k], h.x, ax0);
        ay0 = fmaf(wrow[k], h.y, ay0);
    }
    float accx = ax0 + ax1;
    float accy = ay0 + ay1;

    int base = (b * NN + i) * UU;
    if (LAYER == 1) {
        float gx = 1.0f / (1.0f + __expf(-accx));
        float gy = 1.0f / (1.0f + __expf(-accy));
        if (f2 < UU / 2) {
            const float2 st = ((const float2*)(state + base))[f2];
            float2 rs;
            rs.x = gx * st.x;
            rs.y = gy * st.y;
            ((float2*)(g_rs + base))[f2] = rs;
        } else {
            float2 zz;
            zz.x = gx;
            zz.y = gy;
            ((float2*)(g_z + base))[f2 - UU / 2] = zz;
        }
    } else {
        float htx = tanhf(accx);
        float hty = tanhf(accy);
        const float2 st = ((const float2*)(state + base))[f2];
        const float2 zz = ((const float2*)(g_z + base))[f2];
        float2 o;
        o.x = fmaf(zz.x, st.x, (1.0f - zz.x) * htx);
        o.y = fmaf(zz.y, st.y, (1.0f - zz.y) * hty);
        ((float2*)(out + base))[f2] = o;
    }
}

// ---------------- launch ----------------
extern "C" void kernel_launch(void* const* d_in, const int* in_sizes, int n_in,
                              void* d_out, int out_size) {
    const float* X     = (const float*)d_in[0];
    const float* state = (const float*)d_in[1];
    const float* adj   = (const float*)d_in[2];
    const float* W1    = (const float*)d_in[3];
    const float* a1    = (const float*)d_in[4];
    const float* W2    = (const float*)d_in[5];
    const float* a2    = (const float*)d_in[6];
    float* out = (float*)d_out;

    build_nbr_kernel<<<NN, 128>>>(adj);

    gemm_wmma_kernel<128, 1><<<(BN * NN) / 64, 256>>>(X, state, W1, a1);

    attn_kernel<128, 4, 1><<<dim3(NN, BN / 4), 256>>>(state, out);

    gemm_wmma_kernel<64, 2><<<(BN * NN) / 64, 256>>>(X, state, W2, a2);

    attn_kernel<64, 8, 2><<<dim3(NN, BN / 8), 256>>>(state, out);
}

// round 11
// speedup vs baseline: 1.5520x; 1.0786x over previous
#include <cuda_runtime.h>
#include <cuda_fp16.h>
#include <mma.h>
#include <math.h>
#include <float.h>

using namespace nvcuda;

// Problem constants
#define BN 16
#define NN 1024
#define UU 64
#define KDIM 128
#define MAXD 128
#define ALPHA 0.2f

// ---------------- scratch (device globals; no allocation allowed) ----------------
__device__ __half g_h1[BN * NN * 128];
__device__ __half g_h2[BN * NN * UU];
__device__ float g_ssrc1[BN * NN];
__device__ float g_sdst1[BN * NN];
__device__ float g_ssrc2[BN * NN];
__device__ float g_sdst2[BN * NN];
__device__ float g_z[BN * NN * UU];
__device__ float g_rs[BN * NN * UU];
__device__ int   g_nbr[NN * MAXD];
__device__ int   g_cnt[NN];

// ---------------- neighbor list build (deterministic, ascending j) ----------------
__global__ void build_nbr_kernel(const float* __restrict__ adj) {
    int i = blockIdx.x;
    int tid = threadIdx.x;
    int lane = tid & 31;
    int wid = tid >> 5;
    __shared__ int wcnt[4];
    __shared__ int sbase;
    if (tid == 0) sbase = 0;
    __syncthreads();
    for (int j0 = 0; j0 < NN; j0 += 128) {
        int j = j0 + tid;
        bool p = adj[i * NN + j] > 0.0f;
        unsigned ball = __ballot_sync(0xffffffffu, p);
        if (lane == 0) wcnt[wid] = __popc(ball);
        __syncthreads();
        int off = sbase;
        if (wid > 0) off += wcnt[0];
        if (wid > 1) off += wcnt[1];
        if (wid > 2) off += wcnt[2];
        int tot = wcnt[0] + wcnt[1] + wcnt[2] + wcnt[3];
        if (p) {
            int pos = off + __popc(ball & ((1u << lane) - 1u));
            if (pos < MAXD) g_nbr[i * MAXD + pos] = j;
        }
        __syncthreads();
        if (tid == 0) sbase += tot;
    }
    __syncthreads();
    if (tid == 0) g_cnt[i] = (sbase < MAXD) ? sbase : MAXD;
}

// ---------------- tensor-core fused-concat GEMM (wmma) + scores + fp16 H ----------------
// CTA: 256 thr (8 warps = 2 M-groups x 4 N-groups), M-tile 32, full F, K chunked at 64.
template <int F, int LAYER>
__global__ void __launch_bounds__(256)
gemm_wmma_kernel(const float* __restrict__ X,
                 const float* __restrict__ S,
                 const float* __restrict__ W,
                 const float* __restrict__ a) {
    constexpr int MT = 32;
    constexpr int AS = 72;              // A row stride (halves): 64 + 8
    constexpr int WS = F + 8;           // W row stride (halves)
    constexpr int CS = F + 4;           // C row stride (floats)
    constexpr int NFRAG = F / 64;       // 16-col frags per warp (warp covers F/4)
    constexpr int A_BYTES = MT * AS * 2;
    constexpr int W_BYTES = 64 * WS * 2;
    constexpr int C_BYTES = MT * CS * 4;
    constexpr int STAGE_BYTES = A_BYTES + W_BYTES;
    constexpr int SMEM_BYTES = (C_BYTES > STAGE_BYTES) ? C_BYTES : STAGE_BYTES;

    __shared__ __align__(16) char smem_raw[SMEM_BYTES];
    __half* As = (__half*)smem_raw;                       // [MT][AS]
    __half* Ws = (__half*)(smem_raw + A_BYTES);           // [64][WS]
    float*  Cs = (float*)smem_raw;                        // [MT][CS] (after mainloop)

    const float* Ssrc = (LAYER == 1) ? S : g_rs;
    __half*      H    = (LAYER == 1) ? g_h1 : g_h2;
    float*       ssrc = (LAYER == 1) ? g_ssrc1 : g_ssrc2;
    float*       sdst = (LAYER == 1) ? g_sdst1 : g_sdst2;

    int tid = threadIdx.x;
    int lane = tid & 31;
    int wid = tid >> 5;
    int row0 = blockIdx.x * MT;

    int mw = wid >> 2;                  // 0..1 : 16-row group
    int nw = wid & 3;                   // 0..3 : F/4-col group
    int m0 = mw * 16;
    int n0w = nw * (F / 4);

    wmma::fragment<wmma::accumulator, 16, 16, 16, float> facc[NFRAG];
    for (int nf = 0; nf < NFRAG; nf++) {
        wmma::fill_fragment(facc[nf], 0.0f);
    }

    for (int kc = 0; kc < 2; kc++) {
        const float* src = (kc == 0) ? X : Ssrc;
        // stage A chunk: 32 rows x 64 cols fp32 -> fp16 (512 float4 / 256 thr)
        for (int it = 0; it < 2; it++) {
            int idx = tid + it * 256;        // 0..511
            int r = idx >> 4;
            int c4 = idx & 15;
            float4 v = *(const float4*)(src + (row0 + r) * UU + 4 * c4);
            __half2* dst = (__half2*)(As + r * AS + 4 * c4);
            dst[0] = __floats2half2_rn(v.x, v.y);
            dst[1] = __floats2half2_rn(v.z, v.w);
        }
        // stage W chunk: rows kc*64 .. kc*64+63, F cols fp32 -> fp16
        for (int it = 0; it < F / 16; it++) {
            int idx = tid + it * 256;
            int r = idx / (F / 4);
            int c4 = idx - r * (F / 4);
            float4 v = *(const float4*)(W + (kc * 64 + r) * F + 4 * c4);
            __half2* dst = (__half2*)(Ws + r * WS + 4 * c4);
            dst[0] = __floats2half2_rn(v.x, v.y);
            dst[1] = __floats2half2_rn(v.z, v.w);
        }
        __syncthreads();

        for (int ks = 0; ks < 4; ks++) {
            int k0 = ks * 16;
            wmma::fragment<wmma::matrix_a, 16, 16, 16, __half, wmma::row_major> fa;
            wmma::load_matrix_sync(fa, As + m0 * AS + k0, AS);
            for (int nf = 0; nf < NFRAG; nf++) {
                wmma::fragment<wmma::matrix_b, 16, 16, 16, __half, wmma::row_major> fb;
                wmma::load_matrix_sync(fb, Ws + k0 * WS + n0w + nf * 16, WS);
                wmma::mma_sync(facc[nf], fa, fb, facc[nf]);
            }
        }
        __syncthreads();
    }

    // spill accumulators to shared C (reuses staging memory)
    for (int nf = 0; nf < NFRAG; nf++) {
        wmma::store_matrix_sync(Cs + m0 * CS + n0w + nf * 16, facc[nf], CS, wmma::mem_row_major);
    }
    __syncthreads();

    // epilogue A: fp16 H copy (256 threads over 32 x F/2 half2)
    for (int it = 0; it < MT * F / 512; it++) {
        int idx = tid + it * 256;
        int r = idx / (F / 2);
        int c2 = idx - r * (F / 2);
        float v0 = Cs[r * CS + 2 * c2];
        float v1 = Cs[r * CS + 2 * c2 + 1];
        ((__half2*)(H + (size_t)(row0 + r) * F))[c2] = __floats2half2_rn(v0, v1);
    }

    // epilogue B: fused scores — warp wid handles rows wid*4 .. wid*4+3
    for (int rr = 0; rr < 4; rr++) {
        int r = wid * 4 + rr;
        float s1 = 0.0f;
        float s2 = 0.0f;
        for (int c = lane; c < F; c += 32) {
            float hv = Cs[r * CS + c];
            s1 = fmaf(hv, a[c], s1);
            s2 = fmaf(hv, a[F + c], s2);
        }
        for (int off = 16; off > 0; off >>= 1) {
            s1 += __shfl_xor_sync(0xffffffffu, s1, off);
            s2 += __shfl_xor_sync(0xffffffffu, s2, off);
        }
        if (lane == 0) {
            ssrc[row0 + r] = s1;
            sdst[row0 + r] = s2;
        }
    }
}

// ---------------- masked-softmax attention + fp16 gather + epilogue ----------------
// Block = (i, batch-group BPB). blockDim = BPB * F/4 (thread owns 4 features, 8B loads).
template <int F, int BPB, int LAYER>
__global__ void attn_kernel(const float* __restrict__ state, float* __restrict__ out) {
    constexpr int F4 = F / 4;
    constexpr int NT = BPB * F4;
    constexpr int NWARP = NT / 32;
    const __half* H   = (LAYER == 1) ? g_h1 : g_h2;
    const float* ssrc = (LAYER == 1) ? g_ssrc1 : g_ssrc2;
    const float* sdst = (LAYER == 1) ? g_sdst1 : g_sdst2;

    int i  = blockIdx.x;
    int b0 = blockIdx.y * BPB;
    int tid  = threadIdx.x;
    int lane = tid & 31;
    int wid  = tid >> 5;

    __shared__ int   sj[MAXD];
    __shared__ float sw[BPB][MAXD];
    __shared__ int   scnt;

    if (tid == 0) scnt = g_cnt[i];
    for (int k = tid; k < MAXD; k += NT) sj[k] = g_nbr[i * MAXD + k];
    __syncthreads();
    int cnt = scnt;

    // phase 1: warps loop over batches; per-warp softmax (pre-normalized weights)
    for (int bq = wid; bq < BPB; bq += NWARP) {
        int b = b0 + bq;
        float si = ssrc[b * NN + i];
        const float* sd = sdst + b * NN;
        float ee[MAXD / 32];
        float m = -FLT_MAX;
        for (int u = 0; u < MAXD / 32; u++) {
            int k = lane + 32 * u;
            float e = -FLT_MAX;
            if (k < cnt) {
                float v = si + sd[sj[k]];
                e = (v > 0.0f) ? v : ALPHA * v;
            }
            ee[u] = e;
            m = fmaxf(m, e);
        }
        for (int off = 16; off > 0; off >>= 1) {
            m = fmaxf(m, __shfl_xor_sync(0xffffffffu, m, off));
        }
        float s = 0.0f;
        for (int u = 0; u < MAXD / 32; u++) {
            int k = lane + 32 * u;
            if (k < cnt) {
                float w = __expf(ee[u] - m);
                ee[u] = w;
                s += w;
            }
        }
        for (int off = 16; off > 0; off >>= 1) {
            s += __shfl_xor_sync(0xffffffffu, s, off);
        }
        float inv = 1.0f / s;
        for (int u = 0; u < MAXD / 32; u++) {
            int k = lane + 32 * u;
            if (k < cnt) sw[bq][k] = ee[u] * inv;
        }
    }
    __syncthreads();

    // phase 2: gather-aggregate, 4 features (8 bytes) per thread, unroll-4
    int bb = tid / F4;
    int f4 = tid - bb * F4;
    int b  = b0 + bb;
    const float2* Hb4 = (const float2*)(H + (size_t)(b * NN) * F) + f4;
    const float* wrow = sw[bb];

    float a0x = 0.0f, a0y = 0.0f, a0z = 0.0f, a0w = 0.0f;
    float a1x = 0.0f, a1y = 0.0f, a1z = 0.0f, a1w = 0.0f;
    int k = 0;
    for (; k + 4 <= cnt; k += 4) {
        int j0 = sj[k];
        int j1 = sj[k + 1];
        int j2 = sj[k + 2];
        int j3 = sj[k + 3];
        float w0 = wrow[k];
        float w1 = wrow[k + 1];
        float w2 = wrow[k + 2];
        float w3 = wrow[k + 3];
        float2 r0 = Hb4[(size_t)j0 * F4];
        float2 r1 = Hb4[(size_t)j1 * F4];
        float2 r2 = Hb4[(size_t)j2 * F4];
        float2 r3 = Hb4[(size_t)j3 * F4];
        float2 p00 = __half22float2(*(const __half2*)&r0.x);
        float2 p01 = __half22float2(*(const __half2*)&r0.y);
        float2 p10 = __half22float2(*(const __half2*)&r1.x);
        float2 p11 = __half22float2(*(const __half2*)&r1.y);
        float2 p20 = __half22float2(*(const __half2*)&r2.x);
        float2 p21 = __half22float2(*(const __half2*)&r2.y);
        float2 p30 = __half22float2(*(const __half2*)&r3.x);
        float2 p31 = __half22float2(*(const __half2*)&r3.y);
        a0x = fmaf(w0, p00.x, a0x);
        a0y = fmaf(w0, p00.y, a0y);
        a0z = fmaf(w0, p01.x, a0z);
        a0w = fmaf(w0, p01.y, a0w);
        a1x = fmaf(w1, p10.x, a1x);
        a1y = fmaf(w1, p10.y, a1y);
        a1z = fmaf(w1, p11.x, a1z);
        a1w = fmaf(w1, p11.y, a1w);
        a0x = fmaf(w2, p20.x, a0x);
        a0y = fmaf(w2, p20.y, a0y);
        a0z = fmaf(w2, p21.x, a0z);
        a0w = fmaf(w2, p21.y, a0w);
        a1x = fmaf(w3, p30.x, a1x);
        a1y = fmaf(w3, p30.y, a1y);
        a1z = fmaf(w3, p31.x, a1z);
        a1w = fmaf(w3, p31.y, a1w);
    }
    for (; k < cnt; k++) {
        float wk = wrow[k];
        float2 r0 = Hb4[(size_t)sj[k] * F4];
        float2 p0 = __half22float2(*(const __half2*)&r0.x);
        float2 p1 = __half22float2(*(const __half2*)&r0.y);
        a0x = fmaf(wk, p0.x, a0x);
        a0y = fmaf(wk, p0.y, a0y);
        a0z = fmaf(wk, p1.x, a0z);
        a0w = fmaf(wk, p1.y, a0w);
    }
    float c0 = a0x + a1x;
    float c1 = a0y + a1y;
    float c2 = a0z + a1z;
    float c3 = a0w + a1w;

    int base = (b * NN + i) * UU;
    if (LAYER == 1) {
        float g0 = 1.0f / (1.0f + __expf(-c0));
        float g1 = 1.0f / (1.0f + __expf(-c1));
        float g2 = 1.0f / (1.0f + __expf(-c2));
        float g3 = 1.0f / (1.0f + __expf(-c3));
        if (f4 < UU / 4) {
            const float4 st = ((const float4*)(state + base))[f4];
            float4 rs;
            rs.x = g0 * st.x;
            rs.y = g1 * st.y;
            rs.z = g2 * st.z;
            rs.w = g3 * st.w;
            ((float4*)(g_rs + base))[f4] = rs;
        } else {
            float4 zz;
            zz.x = g0;
            zz.y = g1;
            zz.z = g2;
            zz.w = g3;
            ((float4*)(g_z + base))[f4 - UU / 4] = zz;
        }
    } else {
        float h0 = tanhf(c0);
        float h1 = tanhf(c1);
        float h2 = tanhf(c2);
        float h3 = tanhf(c3);
        const float4 st = ((const float4*)(state + base))[f4];
        const float4 zz = ((const float4*)(g_z + base))[f4];
        float4 o;
        o.x = fmaf(zz.x, st.x, (1.0f - zz.x) * h0);
        o.y = fmaf(zz.y, st.y, (1.0f - zz.y) * h1);
        o.z = fmaf(zz.z, st.z, (1.0f - zz.z) * h2);
        o.w = fmaf(zz.w, st.w, (1.0f - zz.w) * h3);
        ((float4*)(out + base))[f4] = o;
    }
}

// ---------------- launch ----------------
extern "C" void kernel_launch(void* const* d_in, const int* in_sizes, int n_in,
                              void* d_out, int out_size) {
    const float* X     = (const float*)d_in[0];
    const float* state = (const float*)d_in[1];
    const float* adj   = (const float*)d_in[2];
    const float* W1    = (const float*)d_in[3];
    const float* a1    = (const float*)d_in[4];
    const float* W2    = (const float*)d_in[5];
    const float* a2    = (const float*)d_in[6];
    float* out = (float*)d_out;

    build_nbr_kernel<<<NN, 128>>>(adj);

    // layer 1: h1 = [X||state] @ W1 (wmma, fused scores, fp16 H)
    gemm_wmma_kernel<128, 1><<<(BN * NN) / 32, 256>>>(X, state, W1, a1);

    // attention layer 1: BPB=8 -> 256 thr (8 x 32)
    attn_kernel<128, 8, 1><<<dim3(NN, BN / 8), 256>>>(state, out);

    // layer 2: h2 = [X||r*state] @ W2
    gemm_wmma_kernel<64, 2><<<(BN * NN) / 32, 256>>>(X, state, W2, a2);

    // attention layer 2: BPB=16 -> 256 thr (16 x 16)
    attn_kernel<64, 16, 2><<<dim3(NN, BN / 16), 256>>>(state, out);
}